// round 7
// baseline (speedup 1.0000x reference)
#include <cuda_runtime.h>

#define N_USERS 100000
#define N_ITEMS 50000
#define NTOT    150000
#define D       64
#define BATCH   4096
#define NLAYERS 3
#define MAXNNZ  2000000

// -------- static scratch (no allocation allowed) --------
__device__ float g_e0a[(size_t)NTOT * D];
__device__ float g_e1a[(size_t)NTOT * D];
__device__ float g_e2a[(size_t)NTOT * D];
__device__ float g_e3a[(size_t)NTOT * D];
__device__ float g_e0b[(size_t)NTOT * D];
__device__ float g_e1b[(size_t)NTOT * D];
__device__ float g_e2b[(size_t)NTOT * D];
__device__ float g_e3b[(size_t)NTOT * D];
__device__ int   g_rowptr1[NTOT + 1];
__device__ int   g_rowptr2[NTOT + 1];
__device__ int2  g_edges1[MAXNNZ];
__device__ int2  g_edges2[MAXNNZ];

__device__ __forceinline__ float* sel(int w) {
    switch (w) {
        case 0:  return g_e0a;
        case 1:  return g_e1a;
        case 2:  return g_e2a;
        case 3:  return g_e3a;
        case 4:  return g_e0b;
        case 5:  return g_e1b;
        case 6:  return g_e2b;
        default: return g_e3b;
    }
}

// rows[] is sorted; rowptr[r] = lower_bound(rows, r)
__global__ void build_rowptr_kernel(const int* __restrict__ rows, int nnz, int which) {
    int r = blockIdx.x * blockDim.x + threadIdx.x;
    if (r > NTOT) return;
    int lo = 0, hi = nnz;
    while (lo < hi) {
        int mid = (lo + hi) >> 1;
        if (__ldg(rows + mid) < r) lo = mid + 1; else hi = mid;
    }
    (which == 0 ? g_rowptr1 : g_rowptr2)[r] = lo;
}

// pack (col, val) -> int2 edge stream: one LDG.64 per edge in the SpMM
__global__ void pack_edges_kernel(const int* __restrict__ cols,
                                  const float* __restrict__ vals,
                                  int nnz, int which) {
    int i = blockIdx.x * blockDim.x + threadIdx.x;
    if (i >= nnz) return;
    int2 m = make_int2(__ldg(cols + i), __float_as_int(__ldg(vals + i)));
    (which == 0 ? g_edges1 : g_edges2)[i] = m;
}

// concat(user_emb, item_emb) -> e0 buffer
__global__ void pack_kernel(const float* __restrict__ ue, const float* __restrict__ ie,
                            int dst_sel) {
    size_t i = (size_t)blockIdx.x * blockDim.x + threadIdx.x;   // float4 index
    const size_t total = (size_t)NTOT * D / 4;
    if (i >= total) return;
    const size_t nu = (size_t)N_USERS * D / 4;
    float4 v = (i < nu) ? ((const float4*)ue)[i] : ((const float4*)ie)[i - nu];
    ((float4*)sel(dst_sel))[i] = v;
}

// warp-per-row CSR SpMM, half-warp-per-edge:
//   lanes 0-15 process even edges, lanes 16-31 odd edges.
//   One LDG.64 fetches 2 edges' metadata; one LDG.128 fetches 2 edges' 256B rows.
//   Cross-half combine via 4x shfl_xor(16).
__global__ void __launch_bounds__(256)
spmm_kernel(int in_sel, int out_sel, int which) {
    int gw   = (int)((blockIdx.x * blockDim.x + threadIdx.x) >> 5);
    int lane = threadIdx.x & 31;
    if (gw >= NTOT) return;

    const float* __restrict__ in    = sel(in_sel);
    float*       __restrict__ out   = sel(out_sel);
    const int*   __restrict__ rp    = (which == 0) ? g_rowptr1 : g_rowptr2;
    const int2*  __restrict__ edges = (which == 0) ? g_edges1 : g_edges2;

    int s = rp[gw];
    int e = rp[gw + 1];

    int half = lane >> 4;        // 0: even edges, 1: odd edges
    int subl = lane & 15;        // float4 slot within the 256B row

    float4 acc = make_float4(0.f, 0.f, 0.f, 0.f);

    for (int j = s; j < e; j += 8) {       // 8 edges per iteration (4 per half)
        int2 m[4];
        #pragma unroll
        for (int k = 0; k < 4; ++k) {
            int je = j + 2 * k + half;
            int jc = je < e ? je : e - 1;          // clamp index
            m[k] = __ldg(edges + jc);
            if (je >= e) m[k].y = 0;               // val = 0 past end
        }
        #pragma unroll
        for (int k = 0; k < 4; ++k) {
            const float4 ev = *(const float4*)(in + (size_t)m[k].x * D + subl * 4);
            float v = __int_as_float(m[k].y);
            acc.x = fmaf(v, ev.x, acc.x);
            acc.y = fmaf(v, ev.y, acc.y);
            acc.z = fmaf(v, ev.z, acc.z);
            acc.w = fmaf(v, ev.w, acc.w);
        }
    }

    // combine the two half-warp partials
    acc.x += __shfl_xor_sync(0xFFFFFFFFu, acc.x, 16);
    acc.y += __shfl_xor_sync(0xFFFFFFFFu, acc.y, 16);
    acc.z += __shfl_xor_sync(0xFFFFFFFFu, acc.z, 16);
    acc.w += __shfl_xor_sync(0xFFFFFFFFu, acc.w, 16);

    if (half == 0)
        *(float4*)(out + (size_t)gw * D + subl * 4) = acc;
}

// final: out[seg, b, :] = mean(e0..e3)[idx, :]  for the 6 index sets
__global__ void gather_kernel(const int* __restrict__ u1, const int* __restrict__ p1,
                              const int* __restrict__ n1, const int* __restrict__ u2,
                              const int* __restrict__ p2, const int* __restrict__ n2,
                              float* __restrict__ out) {
    int gw   = (int)((blockIdx.x * blockDim.x + threadIdx.x) >> 5);
    int lane = threadIdx.x & 31;
    if (gw >= 6 * BATCH) return;
    int seg = gw / BATCH;
    int b   = gw - seg * BATCH;

    int idx; int g2;
    switch (seg) {
        case 0:  idx = __ldg(u1 + b);           g2 = 0; break;
        case 1:  idx = N_USERS + __ldg(p1 + b); g2 = 0; break;
        case 2:  idx = N_USERS + __ldg(n1 + b); g2 = 0; break;
        case 3:  idx = __ldg(u2 + b);           g2 = 1; break;
        case 4:  idx = N_USERS + __ldg(p2 + b); g2 = 1; break;
        default: idx = N_USERS + __ldg(n2 + b); g2 = 1; break;
    }
    size_t o = (size_t)idx * D + lane * 2;
    const float* t0 = g2 ? g_e0b : g_e0a;
    const float* t1 = g2 ? g_e1b : g_e1a;
    const float* t2 = g2 ? g_e2b : g_e2a;
    const float* t3 = g2 ? g_e3b : g_e3a;
    float2 v0 = *(const float2*)(t0 + o);
    float2 v1 = *(const float2*)(t1 + o);
    float2 v2 = *(const float2*)(t2 + o);
    float2 v3 = *(const float2*)(t3 + o);
    float2 r;
    r.x = (v0.x + v1.x + v2.x + v3.x) * 0.25f;
    r.y = (v0.y + v1.y + v2.y + v3.y) * 0.25f;
    *(float2*)(out + (size_t)gw * D + lane * 2) = r;
}

extern "C" void kernel_launch(void* const* d_in, const int* in_sizes, int n_in,
                              void* d_out, int out_size) {
    const int*   rows1 = (const int*)  d_in[0];
    const int*   cols1 = (const int*)  d_in[1];
    const float* vals1 = (const float*)d_in[2];
    const int*   rows2 = (const int*)  d_in[3];
    const int*   cols2 = (const int*)  d_in[4];
    const float* vals2 = (const float*)d_in[5];
    const float* ue1   = (const float*)d_in[6];
    const float* ie1   = (const float*)d_in[7];
    const float* ue2   = (const float*)d_in[8];
    const float* ie2   = (const float*)d_in[9];
    const int*   u1    = (const int*)  d_in[10];
    const int*   p1    = (const int*)  d_in[11];
    const int*   n1    = (const int*)  d_in[12];
    const int*   u2    = (const int*)  d_in[13];
    const int*   p2    = (const int*)  d_in[14];
    const int*   n2    = (const int*)  d_in[15];
    float* out = (float*)d_out;

    const int nnz1 = in_sizes[0];
    const int nnz2 = in_sizes[3];
    const int TPB = 256;
    const int rowptr_blocks = (NTOT + 1 + TPB - 1) / TPB;
    const int pack_blocks   = (int)(((size_t)NTOT * D / 4 + TPB - 1) / TPB);
    const int spmm_blocks   = (int)(((size_t)NTOT * 32 + TPB - 1) / TPB);
    const int edge_blocks1  = (nnz1 + TPB - 1) / TPB;
    const int edge_blocks2  = (nnz2 + TPB - 1) / TPB;

    // ---- graph 1: e0a -> e1a -> e2a -> e3a ----
    build_rowptr_kernel<<<rowptr_blocks, TPB>>>(rows1, nnz1, 0);
    pack_edges_kernel<<<edge_blocks1, TPB>>>(cols1, vals1, nnz1, 0);
    pack_kernel<<<pack_blocks, TPB>>>(ue1, ie1, 0);
    for (int l = 0; l < NLAYERS; ++l)
        spmm_kernel<<<spmm_blocks, TPB>>>(l, l + 1, 0);

    // ---- graph 2: e0b -> e1b -> e2b -> e3b ----
    build_rowptr_kernel<<<rowptr_blocks, TPB>>>(rows2, nnz2, 1);
    pack_edges_kernel<<<edge_blocks2, TPB>>>(cols2, vals2, nnz2, 1);
    pack_kernel<<<pack_blocks, TPB>>>(ue2, ie2, 4);
    for (int l = 0; l < NLAYERS; ++l)
        spmm_kernel<<<spmm_blocks, TPB>>>(4 + l, 4 + l + 1, 1);

    // ---- batched gathers with on-the-fly layer mean ----
    const int gather_blocks = (6 * BATCH * 32 + TPB - 1) / TPB;
    gather_kernel<<<gather_blocks, TPB>>>(u1, p1, n1, u2, p2, n2, out);
}

// round 9
// speedup vs baseline: 1.0455x; 1.0455x over previous
#include <cuda_runtime.h>
#include <cstdint>

#define N_USERS 100000
#define N_ITEMS 50000
#define NTOT    150000
#define D       64
#define BATCH   4096

// -------- static scratch: e1..e3 per graph (e0 = raw inputs, never packed) ----
__device__ float g_e1a[(size_t)NTOT * D];
__device__ float g_e2a[(size_t)NTOT * D];
__device__ float g_e3a[(size_t)NTOT * D];
__device__ float g_e1b[(size_t)NTOT * D];
__device__ float g_e2b[(size_t)NTOT * D];
__device__ float g_e3b[(size_t)NTOT * D];
__device__ int   g_rowptr1[NTOT + 1];
__device__ int   g_rowptr2[NTOT + 1];

__device__ __forceinline__ float* sel(int w) {
    switch (w) {
        case 0:  return g_e1a;
        case 1:  return g_e2a;
        case 2:  return g_e3a;
        case 3:  return g_e1b;
        case 4:  return g_e2b;
        default: return g_e3b;
    }
}

// rows[] sorted; rowptr[r] = lower_bound(rows, r). Fused: builds both graphs.
__global__ void build_rowptr_kernel(const int* __restrict__ rows1, int nnz1,
                                    const int* __restrict__ rows2, int nnz2) {
    int t = blockIdx.x * blockDim.x + threadIdx.x;
    int g = t > NTOT ? 1 : 0;                  // [0, NTOT] -> g1, [NTOT+1, 2*NTOT+1] -> g2
    int r = g ? t - (NTOT + 1) : t;
    if (r > NTOT) return;
    const int* rows = g ? rows2 : rows1;
    int lo = 0, hi = g ? nnz2 : nnz1;
    while (lo < hi) {
        int mid = (lo + hi) >> 1;
        if (__ldg(rows + mid) < r) lo = mid + 1; else hi = mid;
    }
    (g ? g_rowptr2 : g_rowptr1)[r] = lo;
}

// Fused warp-per-row CSR SpMM over both graphs (2*NTOT rows), half-warp-per-edge.
// SPLIT: layer-1 reads the raw (user_emb, item_emb) pair via base select.
// in1m_* positioned so (in1m + col*D) == ie + (col - N_USERS)*D.
template <bool SPLIT>
__device__ __forceinline__ void spmm_body(
    const int* __restrict__ cols, const float* __restrict__ vals,
    const float* __restrict__ in0, const float* __restrict__ in1m,
    float* __restrict__ out, const int* __restrict__ rp, int row)
{
    int lane = threadIdx.x & 31;
    int s = __ldg(rp + row);
    int e = __ldg(rp + row + 1);

    int half = lane >> 4;        // 0: even edges, 1: odd edges
    int subl = lane & 15;        // float4 slot within the 256B row

    float4 acc = make_float4(0.f, 0.f, 0.f, 0.f);

    int nfull = (e - s) & ~7;
    int j = s;
    for (; j < s + nfull; j += 8) {            // 8 edges per iter, no clamps
        #pragma unroll
        for (int k = 0; k < 4; ++k) {
            int je = j + 2 * k + half;
            int   c = __ldg(cols + je);
            float v = __ldg(vals + je);
            const float* base = SPLIT ? (c < N_USERS ? in0 : in1m) : in0;
            float4 ev = *(const float4*)(base + (size_t)c * D + subl * 4);
            acc.x = fmaf(v, ev.x, acc.x);
            acc.y = fmaf(v, ev.y, acc.y);
            acc.z = fmaf(v, ev.z, acc.z);
            acc.w = fmaf(v, ev.w, acc.w);
        }
    }
    if (j < e) {                                // clamped tail chunk
        #pragma unroll
        for (int k = 0; k < 4; ++k) {
            int je = j + 2 * k + half;
            int jc = je < e ? je : e - 1;
            int   c = __ldg(cols + jc);
            float v = (je < e) ? __ldg(vals + jc) : 0.f;
            const float* base = SPLIT ? (c < N_USERS ? in0 : in1m) : in0;
            float4 ev = *(const float4*)(base + (size_t)c * D + subl * 4);
            acc.x = fmaf(v, ev.x, acc.x);
            acc.y = fmaf(v, ev.y, acc.y);
            acc.z = fmaf(v, ev.z, acc.z);
            acc.w = fmaf(v, ev.w, acc.w);
        }
    }

    acc.x += __shfl_xor_sync(0xFFFFFFFFu, acc.x, 16);
    acc.y += __shfl_xor_sync(0xFFFFFFFFu, acc.y, 16);
    acc.z += __shfl_xor_sync(0xFFFFFFFFu, acc.z, 16);
    acc.w += __shfl_xor_sync(0xFFFFFFFFu, acc.w, 16);

    if (half == 0)
        *(float4*)(out + (size_t)row * D + subl * 4) = acc;
}

__global__ void __launch_bounds__(256)
spmm_first_kernel(const int* __restrict__ cols1, const float* __restrict__ vals1,
                  const int* __restrict__ cols2, const float* __restrict__ vals2,
                  const float* __restrict__ ue1, const float* __restrict__ ie1,
                  const float* __restrict__ ue2, const float* __restrict__ ie2) {
    int gw = (int)((blockIdx.x * blockDim.x + threadIdx.x) >> 5);
    if (gw >= 2 * NTOT) return;
    int g   = gw >= NTOT;
    int row = g ? gw - NTOT : gw;
    const float* ue = g ? ue2 : ue1;
    const float* ie = g ? ie2 : ie1;
    const float* in1m = (const float*)((const char*)ie - (size_t)N_USERS * D * sizeof(float));
    spmm_body<true>(g ? cols2 : cols1, g ? vals2 : vals1, ue, in1m,
                    sel(g ? 3 : 0), g ? g_rowptr2 : g_rowptr1, row);
}

__global__ void __launch_bounds__(256)
spmm_next_kernel(const int* __restrict__ cols1, const float* __restrict__ vals1,
                 const int* __restrict__ cols2, const float* __restrict__ vals2,
                 int l) {   // l = 1 or 2 (layer index of output)
    int gw = (int)((blockIdx.x * blockDim.x + threadIdx.x) >> 5);
    if (gw >= 2 * NTOT) return;
    int g   = gw >= NTOT;
    int row = g ? gw - NTOT : gw;
    const float* in = sel((g ? 3 : 0) + l - 1);
    spmm_body<false>(g ? cols2 : cols1, g ? vals2 : vals1, in, in,
                     sel((g ? 3 : 0) + l), g ? g_rowptr2 : g_rowptr1, row);
}

// final: out[seg, b, :] = mean(e0..e3)[idx, :]; e0 read from raw inputs
__global__ void gather_kernel(const int* __restrict__ u1, const int* __restrict__ p1,
                              const int* __restrict__ n1, const int* __restrict__ u2,
                              const int* __restrict__ p2, const int* __restrict__ n2,
                              const float* __restrict__ ue1, const float* __restrict__ ie1,
                              const float* __restrict__ ue2, const float* __restrict__ ie2,
                              float* __restrict__ out) {
    int gw   = (int)((blockIdx.x * blockDim.x + threadIdx.x) >> 5);
    int lane = threadIdx.x & 31;
    if (gw >= 6 * BATCH) return;
    int seg = gw / BATCH;
    int b   = gw - seg * BATCH;

    int idx; int g2;
    switch (seg) {
        case 0:  idx = __ldg(u1 + b);           g2 = 0; break;
        case 1:  idx = N_USERS + __ldg(p1 + b); g2 = 0; break;
        case 2:  idx = N_USERS + __ldg(n1 + b); g2 = 0; break;
        case 3:  idx = __ldg(u2 + b);           g2 = 1; break;
        case 4:  idx = N_USERS + __ldg(p2 + b); g2 = 1; break;
        default: idx = N_USERS + __ldg(n2 + b); g2 = 1; break;
    }

    const float* e0base;
    if (idx < N_USERS) e0base = (g2 ? ue2 : ue1) + (size_t)idx * D;
    else               e0base = (g2 ? ie2 : ie1) + (size_t)(idx - N_USERS) * D;

    size_t o = (size_t)idx * D + lane * 2;
    const float* t1 = g2 ? g_e1b : g_e1a;
    const float* t2 = g2 ? g_e2b : g_e2a;
    const float* t3 = g2 ? g_e3b : g_e3a;

    float2 v0 = *(const float2*)(e0base + lane * 2);
    float2 v1 = *(const float2*)(t1 + o);
    float2 v2 = *(const float2*)(t2 + o);
    float2 v3 = *(const float2*)(t3 + o);
    float2 r;
    r.x = (v0.x + v1.x + v2.x + v3.x) * 0.25f;
    r.y = (v0.y + v1.y + v2.y + v3.y) * 0.25f;
    *(float2*)(out + (size_t)gw * D + lane * 2) = r;
}

extern "C" void kernel_launch(void* const* d_in, const int* in_sizes, int n_in,
                              void* d_out, int out_size) {
    const int*   rows1 = (const int*)  d_in[0];
    const int*   cols1 = (const int*)  d_in[1];
    const float* vals1 = (const float*)d_in[2];
    const int*   rows2 = (const int*)  d_in[3];
    const int*   cols2 = (const int*)  d_in[4];
    const float* vals2 = (const float*)d_in[5];
    const float* ue1   = (const float*)d_in[6];
    const float* ie1   = (const float*)d_in[7];
    const float* ue2   = (const float*)d_in[8];
    const float* ie2   = (const float*)d_in[9];
    const int*   u1    = (const int*)  d_in[10];
    const int*   p1    = (const int*)  d_in[11];
    const int*   n1    = (const int*)  d_in[12];
    const int*   u2    = (const int*)  d_in[13];
    const int*   p2    = (const int*)  d_in[14];
    const int*   n2    = (const int*)  d_in[15];
    float* out = (float*)d_out;

    const int nnz1 = in_sizes[0];
    const int nnz2 = in_sizes[3];
    const int TPB = 256;
    const int rowptr_blocks = (2 * (NTOT + 1) + TPB - 1) / TPB;
    const int spmm_blocks   = (int)(((size_t)2 * NTOT * 32 + TPB - 1) / TPB);

    build_rowptr_kernel<<<rowptr_blocks, TPB>>>(rows1, nnz1, rows2, nnz2);
    spmm_first_kernel<<<spmm_blocks, TPB>>>(cols1, vals1, cols2, vals2,
                                            ue1, ie1, ue2, ie2);
    spmm_next_kernel<<<spmm_blocks, TPB>>>(cols1, vals1, cols2, vals2, 1);
    spmm_next_kernel<<<spmm_blocks, TPB>>>(cols1, vals1, cols2, vals2, 2);

    const int gather_blocks = (6 * BATCH * 32 + TPB - 1) / TPB;
    gather_kernel<<<gather_blocks, TPB>>>(u1, p1, n1, u2, p2, n2,
                                          ue1, ie1, ue2, ie2, out);
}

// round 12
// speedup vs baseline: 1.2036x; 1.1513x over previous
#include <cuda_runtime.h>
#include <cstdint>

#define N_USERS 100000
#define N_ITEMS 50000
#define NTOT    150000
#define D       64
#define BATCH   4096

// -------- static scratch: e1..e3 per graph (e0 = raw inputs, never packed) ----
__device__ float g_e1a[(size_t)NTOT * D];
__device__ float g_e2a[(size_t)NTOT * D];
__device__ float g_e3a[(size_t)NTOT * D];
__device__ float g_e1b[(size_t)NTOT * D];
__device__ float g_e2b[(size_t)NTOT * D];
__device__ float g_e3b[(size_t)NTOT * D];
__device__ int   g_rowptr1[NTOT + 1];
__device__ int   g_rowptr2[NTOT + 1];

// compile-time buffer selection -> immediate addresses in SASS, no host API
template <int W> __device__ __forceinline__ float* buf();
template <> __device__ __forceinline__ float* buf<0>() { return g_e1a; }
template <> __device__ __forceinline__ float* buf<1>() { return g_e2a; }
template <> __device__ __forceinline__ float* buf<2>() { return g_e3a; }
template <> __device__ __forceinline__ float* buf<3>() { return g_e1b; }
template <> __device__ __forceinline__ float* buf<4>() { return g_e2b; }
template <> __device__ __forceinline__ float* buf<5>() { return g_e3b; }
template <int W> __device__ __forceinline__ int* rptr() {
    return W == 0 ? g_rowptr1 : g_rowptr2;
}

// rows[] sorted; rowptr[r] = lower_bound(rows, r)
template <int WHICH>
__global__ void build_rowptr_kernel(const int* __restrict__ rows, int nnz) {
    int r = blockIdx.x * blockDim.x + threadIdx.x;
    if (r > NTOT) return;
    int lo = 0, hi = nnz;
    while (lo < hi) {
        int mid = (lo + hi) >> 1;
        if (__ldg(rows + mid) < r) lo = mid + 1; else hi = mid;
    }
    rptr<WHICH>()[r] = lo;
}

// warp-per-row CSR SpMM, half-warp-per-edge:
//   lanes 0-15 even edges, 16-31 odd edges; one LDG.128 covers 2 edges' rows.
// SPLIT: layer-1 reads raw (user_emb, item_emb); in1m pre-offset by -N_USERS*D.
template <bool SPLIT>
__device__ __forceinline__ void spmm_body(
    const int* __restrict__ cols, const float* __restrict__ vals,
    const float* __restrict__ in0, const float* __restrict__ in1m,
    float* __restrict__ out, const int* __restrict__ rp)
{
    int gw   = (int)((blockIdx.x * blockDim.x + threadIdx.x) >> 5);
    int lane = threadIdx.x & 31;
    if (gw >= NTOT) return;

    int s = __ldg(rp + gw);
    int e = __ldg(rp + gw + 1);

    int half = lane >> 4;
    int subl = lane & 15;

    float4 acc = make_float4(0.f, 0.f, 0.f, 0.f);

    int nfull = (e - s) & ~7;
    int j = s;
    for (; j < s + nfull; j += 8) {            // 8 edges per iter, no clamps
        #pragma unroll
        for (int k = 0; k < 4; ++k) {
            int je = j + 2 * k + half;
            int   c = __ldg(cols + je);
            float v = __ldg(vals + je);
            const float* base = SPLIT ? (c < N_USERS ? in0 : in1m) : in0;
            float4 ev = __ldcg((const float4*)(base + (size_t)c * D + subl * 4));
            acc.x = fmaf(v, ev.x, acc.x);
            acc.y = fmaf(v, ev.y, acc.y);
            acc.z = fmaf(v, ev.z, acc.z);
            acc.w = fmaf(v, ev.w, acc.w);
        }
    }
    if (j < e) {                                // one clamped tail chunk
        #pragma unroll
        for (int k = 0; k < 4; ++k) {
            int je = j + 2 * k + half;
            int jc = je < e ? je : e - 1;
            int   c = __ldg(cols + jc);
            float v = (je < e) ? __ldg(vals + jc) : 0.f;
            const float* base = SPLIT ? (c < N_USERS ? in0 : in1m) : in0;
            float4 ev = __ldcg((const float4*)(base + (size_t)c * D + subl * 4));
            acc.x = fmaf(v, ev.x, acc.x);
            acc.y = fmaf(v, ev.y, acc.y);
            acc.z = fmaf(v, ev.z, acc.z);
            acc.w = fmaf(v, ev.w, acc.w);
        }
    }

    acc.x += __shfl_xor_sync(0xFFFFFFFFu, acc.x, 16);
    acc.y += __shfl_xor_sync(0xFFFFFFFFu, acc.y, 16);
    acc.z += __shfl_xor_sync(0xFFFFFFFFu, acc.z, 16);
    acc.w += __shfl_xor_sync(0xFFFFFFFFu, acc.w, 16);

    if (half == 0)
        *(float4*)(out + (size_t)gw * D + subl * 4) = acc;
}

template <int OUT, int WHICH>
__global__ void __launch_bounds__(256, 8)
spmm_first_kernel(const int* __restrict__ cols, const float* __restrict__ vals,
                  const float* __restrict__ ue, const float* __restrict__ ie) {
    const float* in1m = (const float*)((const char*)ie - (size_t)N_USERS * D * sizeof(float));
    spmm_body<true>(cols, vals, ue, in1m, buf<OUT>(), rptr<WHICH>());
}

template <int IN, int OUT, int WHICH>
__global__ void __launch_bounds__(256, 8)
spmm_next_kernel(const int* __restrict__ cols, const float* __restrict__ vals) {
    spmm_body<false>(cols, vals, buf<IN>(), buf<IN>(), buf<OUT>(), rptr<WHICH>());
}

// final: out[seg, b, :] = mean(e0..e3)[idx, :]; e0 read from raw inputs
__global__ void gather_kernel(const int* __restrict__ u1, const int* __restrict__ p1,
                              const int* __restrict__ n1, const int* __restrict__ u2,
                              const int* __restrict__ p2, const int* __restrict__ n2,
                              const float* __restrict__ ue1, const float* __restrict__ ie1,
                              const float* __restrict__ ue2, const float* __restrict__ ie2,
                              float* __restrict__ out) {
    int gw   = (int)((blockIdx.x * blockDim.x + threadIdx.x) >> 5);
    int lane = threadIdx.x & 31;
    if (gw >= 6 * BATCH) return;
    int seg = gw / BATCH;
    int b   = gw - seg * BATCH;

    int idx; int g2;
    switch (seg) {
        case 0:  idx = __ldg(u1 + b);           g2 = 0; break;
        case 1:  idx = N_USERS + __ldg(p1 + b); g2 = 0; break;
        case 2:  idx = N_USERS + __ldg(n1 + b); g2 = 0; break;
        case 3:  idx = __ldg(u2 + b);           g2 = 1; break;
        case 4:  idx = N_USERS + __ldg(p2 + b); g2 = 1; break;
        default: idx = N_USERS + __ldg(n2 + b); g2 = 1; break;
    }

    const float* e0base;
    if (idx < N_USERS) e0base = (g2 ? ue2 : ue1) + (size_t)idx * D;
    else               e0base = (g2 ? ie2 : ie1) + (size_t)(idx - N_USERS) * D;

    size_t o = (size_t)idx * D + lane * 2;
    const float* t1 = g2 ? g_e1b : g_e1a;
    const float* t2 = g2 ? g_e2b : g_e2a;
    const float* t3 = g2 ? g_e3b : g_e3a;

    float2 v0 = *(const float2*)(e0base + lane * 2);
    float2 v1 = *(const float2*)(t1 + o);
    float2 v2 = *(const float2*)(t2 + o);
    float2 v3 = *(const float2*)(t3 + o);
    float2 r;
    r.x = (v0.x + v1.x + v2.x + v3.x) * 0.25f;
    r.y = (v0.y + v1.y + v2.y + v3.y) * 0.25f;
    *(float2*)(out + (size_t)gw * D + lane * 2) = r;
}

extern "C" void kernel_launch(void* const* d_in, const int* in_sizes, int n_in,
                              void* d_out, int out_size) {
    const int*   rows1 = (const int*)  d_in[0];
    const int*   cols1 = (const int*)  d_in[1];
    const float* vals1 = (const float*)d_in[2];
    const int*   rows2 = (const int*)  d_in[3];
    const int*   cols2 = (const int*)  d_in[4];
    const float* vals2 = (const float*)d_in[5];
    const float* ue1   = (const float*)d_in[6];
    const float* ie1   = (const float*)d_in[7];
    const float* ue2   = (const float*)d_in[8];
    const float* ie2   = (const float*)d_in[9];
    const int*   u1    = (const int*)  d_in[10];
    const int*   p1    = (const int*)  d_in[11];
    const int*   n1    = (const int*)  d_in[12];
    const int*   u2    = (const int*)  d_in[13];
    const int*   p2    = (const int*)  d_in[14];
    const int*   n2    = (const int*)  d_in[15];
    float* out = (float*)d_out;

    const int nnz1 = in_sizes[0];
    const int nnz2 = in_sizes[3];
    const int TPB = 256;
    const int rowptr_blocks = (NTOT + 1 + TPB - 1) / TPB;
    const int spmm_blocks   = (int)(((size_t)NTOT * 32 + TPB - 1) / TPB);

    // ---- graph 1: (ue1|ie1) -> e1a -> e2a -> e3a ----
    build_rowptr_kernel<0><<<rowptr_blocks, TPB>>>(rows1, nnz1);
    spmm_first_kernel<0, 0><<<spmm_blocks, TPB>>>(cols1, vals1, ue1, ie1);
    spmm_next_kernel<0, 1, 0><<<spmm_blocks, TPB>>>(cols1, vals1);
    spmm_next_kernel<1, 2, 0><<<spmm_blocks, TPB>>>(cols1, vals1);

    // ---- graph 2: (ue2|ie2) -> e1b -> e2b -> e3b ----
    build_rowptr_kernel<1><<<rowptr_blocks, TPB>>>(rows2, nnz2);
    spmm_first_kernel<3, 1><<<spmm_blocks, TPB>>>(cols2, vals2, ue2, ie2);
    spmm_next_kernel<3, 4, 1><<<spmm_blocks, TPB>>>(cols2, vals2);
    spmm_next_kernel<4, 5, 1><<<spmm_blocks, TPB>>>(cols2, vals2);

    // ---- batched gathers with on-the-fly layer mean (e0 from raw inputs) ----
    const int gather_blocks = (6 * BATCH * 32 + TPB - 1) / TPB;
    gather_kernel<<<gather_blocks, TPB>>>(u1, p1, n1, u2, p2, n2,
                                          ue1, ie1, ue2, ie2, out);
}

// round 13
// speedup vs baseline: 1.6170x; 1.3435x over previous
#include <cuda_runtime.h>
#include <cstdint>

#define N_USERS 100000
#define N_ITEMS 50000
#define NTOT    150000
#define D       64
#define BATCH   4096

// -------- static scratch: e1,e2 per graph (e0 = raw inputs; e3 fused) --------
__device__ float g_e1a[(size_t)NTOT * D];
__device__ float g_e2a[(size_t)NTOT * D];
__device__ float g_e1b[(size_t)NTOT * D];
__device__ float g_e2b[(size_t)NTOT * D];
__device__ int   g_rowptr1[NTOT + 1];
__device__ int   g_rowptr2[NTOT + 1];

// compile-time buffer selection -> immediate addresses in SASS
template <int W> __device__ __forceinline__ float* buf();
template <> __device__ __forceinline__ float* buf<0>() { return g_e1a; }
template <> __device__ __forceinline__ float* buf<1>() { return g_e2a; }
template <> __device__ __forceinline__ float* buf<2>() { return g_e1b; }
template <> __device__ __forceinline__ float* buf<3>() { return g_e2b; }
template <int W> __device__ __forceinline__ int* rptr() {
    return W == 0 ? g_rowptr1 : g_rowptr2;
}

// rows[] sorted; rowptr[r] = lower_bound(rows, r)
template <int WHICH>
__global__ void build_rowptr_kernel(const int* __restrict__ rows, int nnz) {
    int r = blockIdx.x * blockDim.x + threadIdx.x;
    if (r > NTOT) return;
    int lo = 0, hi = nnz;
    while (lo < hi) {
        int mid = (lo + hi) >> 1;
        if (__ldg(rows + mid) < r) lo = mid + 1; else hi = mid;
    }
    rptr<WHICH>()[r] = lo;
}

// Half-warp-per-edge CSR row reduction: returns this row's 64-dim sum as
// float4 per (half==0, subl) lane. SPLIT: gather from raw (ue, ie) pair.
template <bool SPLIT>
__device__ __forceinline__ float4 row_reduce(
    const int* __restrict__ cols, const float* __restrict__ vals,
    const float* __restrict__ in0, const float* __restrict__ in1m,
    int s, int e, int half, int subl)
{
    float4 acc = make_float4(0.f, 0.f, 0.f, 0.f);

    int nfull = (e - s) & ~7;
    int j = s;
    for (; j < s + nfull; j += 8) {            // 8 edges per iter, no clamps
        #pragma unroll
        for (int k = 0; k < 4; ++k) {
            int je = j + 2 * k + half;
            int   c = __ldg(cols + je);
            float v = __ldg(vals + je);
            const float* base = SPLIT ? (c < N_USERS ? in0 : in1m) : in0;
            float4 ev = __ldcg((const float4*)(base + (size_t)c * D + subl * 4));
            acc.x = fmaf(v, ev.x, acc.x);
            acc.y = fmaf(v, ev.y, acc.y);
            acc.z = fmaf(v, ev.z, acc.z);
            acc.w = fmaf(v, ev.w, acc.w);
        }
    }
    if (j < e) {                                // one clamped tail chunk
        #pragma unroll
        for (int k = 0; k < 4; ++k) {
            int je = j + 2 * k + half;
            int jc = je < e ? je : e - 1;
            int   c = __ldg(cols + jc);
            float v = (je < e) ? __ldg(vals + jc) : 0.f;
            const float* base = SPLIT ? (c < N_USERS ? in0 : in1m) : in0;
            float4 ev = __ldcg((const float4*)(base + (size_t)c * D + subl * 4));
            acc.x = fmaf(v, ev.x, acc.x);
            acc.y = fmaf(v, ev.y, acc.y);
            acc.z = fmaf(v, ev.z, acc.z);
            acc.w = fmaf(v, ev.w, acc.w);
        }
    }

    acc.x += __shfl_xor_sync(0xFFFFFFFFu, acc.x, 16);
    acc.y += __shfl_xor_sync(0xFFFFFFFFu, acc.y, 16);
    acc.z += __shfl_xor_sync(0xFFFFFFFFu, acc.z, 16);
    acc.w += __shfl_xor_sync(0xFFFFFFFFu, acc.w, 16);
    return acc;
}

template <int OUT, int WHICH>
__global__ void __launch_bounds__(256, 8)
spmm_first_kernel(const int* __restrict__ cols, const float* __restrict__ vals,
                  const float* __restrict__ ue, const float* __restrict__ ie) {
    int gw   = (int)((blockIdx.x * blockDim.x + threadIdx.x) >> 5);
    int lane = threadIdx.x & 31;
    if (gw >= NTOT) return;
    const int* rp = rptr<WHICH>();
    int s = __ldg(rp + gw);
    int e = __ldg(rp + gw + 1);
    const float* in1m = (const float*)((const char*)ie - (size_t)N_USERS * D * sizeof(float));
    int half = lane >> 4, subl = lane & 15;
    float4 acc = row_reduce<true>(cols, vals, ue, in1m, s, e, half, subl);
    if (half == 0)
        *(float4*)(buf<OUT>() + (size_t)gw * D + subl * 4) = acc;
}

template <int IN, int OUT, int WHICH>
__global__ void __launch_bounds__(256, 8)
spmm_next_kernel(const int* __restrict__ cols, const float* __restrict__ vals) {
    int gw   = (int)((blockIdx.x * blockDim.x + threadIdx.x) >> 5);
    int lane = threadIdx.x & 31;
    if (gw >= NTOT) return;
    const int* rp = rptr<WHICH>();
    int s = __ldg(rp + gw);
    int e = __ldg(rp + gw + 1);
    int half = lane >> 4, subl = lane & 15;
    float4 acc = row_reduce<false>(cols, vals, buf<IN>(), buf<IN>(), s, e, half, subl);
    if (half == 0)
        *(float4*)(buf<OUT>() + (size_t)gw * D + subl * 4) = acc;
}

// Fused layer-3 + mean + gather:
//   out[seg,b,:] = (e0[idx] + e1[idx] + e2[idx] + (A·e2)[idx]) / 4
// (A·e2)[idx] computed on the fly — only ~24.6K rows instead of 300K.
__global__ void __launch_bounds__(256, 8)
gather3_kernel(const int* __restrict__ u1, const int* __restrict__ p1,
               const int* __restrict__ n1, const int* __restrict__ u2,
               const int* __restrict__ p2, const int* __restrict__ n2,
               const int* __restrict__ cols1, const float* __restrict__ vals1,
               const int* __restrict__ cols2, const float* __restrict__ vals2,
               const float* __restrict__ ue1, const float* __restrict__ ie1,
               const float* __restrict__ ue2, const float* __restrict__ ie2,
               float* __restrict__ out) {
    int gw   = (int)((blockIdx.x * blockDim.x + threadIdx.x) >> 5);
    int lane = threadIdx.x & 31;
    if (gw >= 6 * BATCH) return;
    int seg = gw / BATCH;
    int b   = gw - seg * BATCH;

    int idx; int g2;
    switch (seg) {
        case 0:  idx = __ldg(u1 + b);           g2 = 0; break;
        case 1:  idx = N_USERS + __ldg(p1 + b); g2 = 0; break;
        case 2:  idx = N_USERS + __ldg(n1 + b); g2 = 0; break;
        case 3:  idx = __ldg(u2 + b);           g2 = 1; break;
        case 4:  idx = N_USERS + __ldg(p2 + b); g2 = 1; break;
        default: idx = N_USERS + __ldg(n2 + b); g2 = 1; break;
    }

    const int*   rp   = g2 ? g_rowptr2 : g_rowptr1;
    const int*   cols = g2 ? cols2 : cols1;
    const float* vals = g2 ? vals2 : vals1;
    const float* e1t  = g2 ? g_e1b : g_e1a;
    const float* e2t  = g2 ? g_e2b : g_e2a;

    int s = __ldg(rp + idx);
    int e = __ldg(rp + idx + 1);
    int half = lane >> 4, subl = lane & 15;

    // e3[idx] on the fly from e2
    float4 acc = row_reduce<false>(cols, vals, e2t, e2t, s, e, half, subl);

    if (half == 0) {
        const float* e0base;
        if (idx < N_USERS) e0base = (g2 ? ue2 : ue1) + (size_t)idx * D;
        else               e0base = (g2 ? ie2 : ie1) + (size_t)(idx - N_USERS) * D;
        size_t o = (size_t)idx * D + subl * 4;
        float4 v0 = *(const float4*)(e0base + subl * 4);
        float4 v1 = *(const float4*)(e1t + o);
        float4 v2 = *(const float4*)(e2t + o);
        float4 r;
        r.x = (v0.x + v1.x + v2.x + acc.x) * 0.25f;
        r.y = (v0.y + v1.y + v2.y + acc.y) * 0.25f;
        r.z = (v0.z + v1.z + v2.z + acc.z) * 0.25f;
        r.w = (v0.w + v1.w + v2.w + acc.w) * 0.25f;
        *(float4*)(out + (size_t)gw * D + subl * 4) = r;
    }
}

extern "C" void kernel_launch(void* const* d_in, const int* in_sizes, int n_in,
                              void* d_out, int out_size) {
    const int*   rows1 = (const int*)  d_in[0];
    const int*   cols1 = (const int*)  d_in[1];
    const float* vals1 = (const float*)d_in[2];
    const int*   rows2 = (const int*)  d_in[3];
    const int*   cols2 = (const int*)  d_in[4];
    const float* vals2 = (const float*)d_in[5];
    const float* ue1   = (const float*)d_in[6];
    const float* ie1   = (const float*)d_in[7];
    const float* ue2   = (const float*)d_in[8];
    const float* ie2   = (const float*)d_in[9];
    const int*   u1    = (const int*)  d_in[10];
    const int*   p1    = (const int*)  d_in[11];
    const int*   n1    = (const int*)  d_in[12];
    const int*   u2    = (const int*)  d_in[13];
    const int*   p2    = (const int*)  d_in[14];
    const int*   n2    = (const int*)  d_in[15];
    float* out = (float*)d_out;

    const int nnz1 = in_sizes[0];
    const int nnz2 = in_sizes[3];
    const int TPB = 256;
    const int rowptr_blocks = (NTOT + 1 + TPB - 1) / TPB;
    const int spmm_blocks   = (int)(((size_t)NTOT * 32 + TPB - 1) / TPB);

    // ---- graph 1: (ue1|ie1) -> e1a -> e2a ----
    build_rowptr_kernel<0><<<rowptr_blocks, TPB>>>(rows1, nnz1);
    spmm_first_kernel<0, 0><<<spmm_blocks, TPB>>>(cols1, vals1, ue1, ie1);
    spmm_next_kernel<0, 1, 0><<<spmm_blocks, TPB>>>(cols1, vals1);

    // ---- graph 2: (ue2|ie2) -> e1b -> e2b ----
    build_rowptr_kernel<1><<<rowptr_blocks, TPB>>>(rows2, nnz2);
    spmm_first_kernel<2, 1><<<spmm_blocks, TPB>>>(cols2, vals2, ue2, ie2);
    spmm_next_kernel<2, 3, 1><<<spmm_blocks, TPB>>>(cols2, vals2);

    // ---- fused layer-3 + mean + gather ----
    const int gather_blocks = (6 * BATCH * 32 + TPB - 1) / TPB;
    gather3_kernel<<<gather_blocks, TPB>>>(u1, p1, n1, u2, p2, n2,
                                           cols1, vals1, cols2, vals2,
                                           ue1, ie1, ue2, ie2, out);
}

// round 15
// speedup vs baseline: 1.8158x; 1.1229x over previous
#include <cuda_runtime.h>
#include <cuda_fp16.h>
#include <cstdint>
#include <cstring>

#define N_USERS 100000
#define N_ITEMS 50000
#define NTOT    150000
#define D       64
#define BATCH   4096

// -------- static scratch: fp16 e1,e2 per graph (e0 = raw fp32 inputs) --------
__device__ __half g_h1a[(size_t)NTOT * D];
__device__ __half g_h2a[(size_t)NTOT * D];
__device__ __half g_h1b[(size_t)NTOT * D];
__device__ __half g_h2b[(size_t)NTOT * D];
__device__ int    g_rowptr1[NTOT + 1];
__device__ int    g_rowptr2[NTOT + 1];

template <int W> __device__ __forceinline__ __half* hbuf();
template <> __device__ __forceinline__ __half* hbuf<0>() { return g_h1a; }
template <> __device__ __forceinline__ __half* hbuf<1>() { return g_h2a; }
template <> __device__ __forceinline__ __half* hbuf<2>() { return g_h1b; }
template <> __device__ __forceinline__ __half* hbuf<3>() { return g_h2b; }
template <int W> __device__ __forceinline__ int* rptr() {
    return W == 0 ? g_rowptr1 : g_rowptr2;
}

// Scan-based rowptr: rp[r] = lower_bound(rows, r). Streaming, no binary search.
template <int WHICH>
__global__ void rowptr_scan_kernel(const int* __restrict__ rows, int nnz) {
    int i = blockIdx.x * blockDim.x + threadIdx.x;
    if (i >= nnz) return;
    int* rp  = rptr<WHICH>();
    int cur  = __ldg(rows + i);
    int prev = (i == 0) ? -1 : __ldg(rows + i - 1);
    for (int r = prev + 1; r <= cur; ++r) rp[r] = i;     // (prev, cur] -> i
    if (i == nnz - 1)
        for (int r = cur + 1; r <= NTOT; ++r) rp[r] = nnz;
}

__device__ __forceinline__ void store_half4(__half* out, size_t off, float4 a) {
    __half2 h0 = __floats2half2_rn(a.x, a.y);
    __half2 h1 = __floats2half2_rn(a.z, a.w);
    uint2 u;
    memcpy(&u.x, &h0, 4);
    memcpy(&u.y, &h1, 4);
    *(uint2*)(out + off) = u;
}

// fp32-gather row reduction (layer 1): half-warp per edge, LDG.128 rows.
__device__ __forceinline__ float4 row_reduce_f32(
    const int* __restrict__ cols, const float* __restrict__ vals,
    const float* __restrict__ in0, const float* __restrict__ in1m,
    int s, int e, int half, int subl)
{
    float4 acc = make_float4(0.f, 0.f, 0.f, 0.f);
    int nfull = (e - s) & ~7;
    int j = s;
    for (; j < s + nfull; j += 8) {
        #pragma unroll
        for (int k = 0; k < 4; ++k) {
            int je = j + 2 * k + half;
            int   c = __ldg(cols + je);
            float v = __ldg(vals + je);
            const float* base = (c < N_USERS) ? in0 : in1m;
            float4 ev = __ldcg((const float4*)(base + (size_t)c * D + subl * 4));
            acc.x = fmaf(v, ev.x, acc.x);
            acc.y = fmaf(v, ev.y, acc.y);
            acc.z = fmaf(v, ev.z, acc.z);
            acc.w = fmaf(v, ev.w, acc.w);
        }
    }
    if (j < e) {
        #pragma unroll
        for (int k = 0; k < 4; ++k) {
            int je = j + 2 * k + half;
            int jc = je < e ? je : e - 1;
            int   c = __ldg(cols + jc);
            float v = (je < e) ? __ldg(vals + jc) : 0.f;
            const float* base = (c < N_USERS) ? in0 : in1m;
            float4 ev = __ldcg((const float4*)(base + (size_t)c * D + subl * 4));
            acc.x = fmaf(v, ev.x, acc.x);
            acc.y = fmaf(v, ev.y, acc.y);
            acc.z = fmaf(v, ev.z, acc.z);
            acc.w = fmaf(v, ev.w, acc.w);
        }
    }
    acc.x += __shfl_xor_sync(0xFFFFFFFFu, acc.x, 16);
    acc.y += __shfl_xor_sync(0xFFFFFFFFu, acc.y, 16);
    acc.z += __shfl_xor_sync(0xFFFFFFFFu, acc.z, 16);
    acc.w += __shfl_xor_sync(0xFFFFFFFFu, acc.w, 16);
    return acc;
}

// fp16-gather row reduction: half-warp per edge, LDG.64 rows (128B/row), fp32 acc.
__device__ __forceinline__ float4 row_reduce_f16(
    const int* __restrict__ cols, const float* __restrict__ vals,
    const __half* __restrict__ tab, int s, int e, int half, int subl)
{
    float4 acc = make_float4(0.f, 0.f, 0.f, 0.f);
    int nfull = (e - s) & ~7;
    int j = s;
    for (; j < s + nfull; j += 8) {
        #pragma unroll
        for (int k = 0; k < 4; ++k) {
            int je = j + 2 * k + half;
            int   c = __ldg(cols + je);
            float v = __ldg(vals + je);
            uint2 u = __ldcg((const uint2*)(tab + (size_t)c * D + subl * 4));
            __half2 h0, h1;
            memcpy(&h0, &u.x, 4);
            memcpy(&h1, &u.y, 4);
            float2 f0 = __half22float2(h0);
            float2 f1 = __half22float2(h1);
            acc.x = fmaf(v, f0.x, acc.x);
            acc.y = fmaf(v, f0.y, acc.y);
            acc.z = fmaf(v, f1.x, acc.z);
            acc.w = fmaf(v, f1.y, acc.w);
        }
    }
    if (j < e) {
        #pragma unroll
        for (int k = 0; k < 4; ++k) {
            int je = j + 2 * k + half;
            int jc = je < e ? je : e - 1;
            int   c = __ldg(cols + jc);
            float v = (je < e) ? __ldg(vals + jc) : 0.f;
            uint2 u = __ldcg((const uint2*)(tab + (size_t)c * D + subl * 4));
            __half2 h0, h1;
            memcpy(&h0, &u.x, 4);
            memcpy(&h1, &u.y, 4);
            float2 f0 = __half22float2(h0);
            float2 f1 = __half22float2(h1);
            acc.x = fmaf(v, f0.x, acc.x);
            acc.y = fmaf(v, f0.y, acc.y);
            acc.z = fmaf(v, f1.x, acc.z);
            acc.w = fmaf(v, f1.y, acc.w);
        }
    }
    acc.x += __shfl_xor_sync(0xFFFFFFFFu, acc.x, 16);
    acc.y += __shfl_xor_sync(0xFFFFFFFFu, acc.y, 16);
    acc.z += __shfl_xor_sync(0xFFFFFFFFu, acc.z, 16);
    acc.w += __shfl_xor_sync(0xFFFFFFFFu, acc.w, 16);
    return acc;
}

// Layer 1: fp32 raw gather -> fp16 store
template <int OUT, int WHICH>
__global__ void __launch_bounds__(256, 8)
spmm_first_kernel(const int* __restrict__ cols, const float* __restrict__ vals,
                  const float* __restrict__ ue, const float* __restrict__ ie) {
    int gw   = (int)((blockIdx.x * blockDim.x + threadIdx.x) >> 5);
    int lane = threadIdx.x & 31;
    if (gw >= NTOT) return;
    const int* rp = rptr<WHICH>();
    int s = __ldg(rp + gw);
    int e = __ldg(rp + gw + 1);
    const float* in1m = (const float*)((const char*)ie - (size_t)N_USERS * D * sizeof(float));
    int half = lane >> 4, subl = lane & 15;
    float4 acc = row_reduce_f32(cols, vals, ue, in1m, s, e, half, subl);
    if (half == 0)
        store_half4(hbuf<OUT>(), (size_t)gw * D + subl * 4, acc);
}

// Layer 2: fp16 gather -> fp16 store
template <int IN, int OUT, int WHICH>
__global__ void __launch_bounds__(256, 8)
spmm_mid_kernel(const int* __restrict__ cols, const float* __restrict__ vals) {
    int gw   = (int)((blockIdx.x * blockDim.x + threadIdx.x) >> 5);
    int lane = threadIdx.x & 31;
    if (gw >= NTOT) return;
    const int* rp = rptr<WHICH>();
    int s = __ldg(rp + gw);
    int e = __ldg(rp + gw + 1);
    int half = lane >> 4, subl = lane & 15;
    float4 acc = row_reduce_f16(cols, vals, hbuf<IN>(), s, e, half, subl);
    if (half == 0)
        store_half4(hbuf<OUT>(), (size_t)gw * D + subl * 4, acc);
}

// Fused layer-3 + mean + gather (fp32 output):
//   out[seg,b,:] = (e0[idx] + e1h[idx] + e2h[idx] + (A·e2h)[idx]) / 4
__global__ void __launch_bounds__(256, 8)
gather3_kernel(const int* __restrict__ u1, const int* __restrict__ p1,
               const int* __restrict__ n1, const int* __restrict__ u2,
               const int* __restrict__ p2, const int* __restrict__ n2,
               const int* __restrict__ cols1, const float* __restrict__ vals1,
               const int* __restrict__ cols2, const float* __restrict__ vals2,
               const float* __restrict__ ue1, const float* __restrict__ ie1,
               const float* __restrict__ ue2, const float* __restrict__ ie2,
               float* __restrict__ out) {
    int gw   = (int)((blockIdx.x * blockDim.x + threadIdx.x) >> 5);
    int lane = threadIdx.x & 31;
    if (gw >= 6 * BATCH) return;
    int seg = gw / BATCH;
    int b   = gw - seg * BATCH;

    int idx; int g2;
    switch (seg) {
        case 0:  idx = __ldg(u1 + b);           g2 = 0; break;
        case 1:  idx = N_USERS + __ldg(p1 + b); g2 = 0; break;
        case 2:  idx = N_USERS + __ldg(n1 + b); g2 = 0; break;
        case 3:  idx = __ldg(u2 + b);           g2 = 1; break;
        case 4:  idx = N_USERS + __ldg(p2 + b); g2 = 1; break;
        default: idx = N_USERS + __ldg(n2 + b); g2 = 1; break;
    }

    const int*    rp   = g2 ? g_rowptr2 : g_rowptr1;
    const int*    cols = g2 ? cols2 : cols1;
    const float*  vals = g2 ? vals2 : vals1;
    const __half* e1t  = g2 ? g_h1b : g_h1a;
    const __half* e2t  = g2 ? g_h2b : g_h2a;

    int s = __ldg(rp + idx);
    int e = __ldg(rp + idx + 1);
    int half = lane >> 4, subl = lane & 15;

    // e3[idx] on the fly from fp16 e2
    float4 acc = row_reduce_f16(cols, vals, e2t, s, e, half, subl);

    if (half == 0) {
        const float* e0base;
        if (idx < N_USERS) e0base = (g2 ? ue2 : ue1) + (size_t)idx * D;
        else               e0base = (g2 ? ie2 : ie1) + (size_t)(idx - N_USERS) * D;
        size_t o = (size_t)idx * D + subl * 4;
        float4 v0 = *(const float4*)(e0base + subl * 4);

        uint2 ua = *(const uint2*)(e1t + o);
        uint2 ub = *(const uint2*)(e2t + o);
        __half2 a0, a1, b0, b1;
        memcpy(&a0, &ua.x, 4); memcpy(&a1, &ua.y, 4);
        memcpy(&b0, &ub.x, 4); memcpy(&b1, &ub.y, 4);
        float2 f1lo = __half22float2(a0), f1hi = __half22float2(a1);
        float2 f2lo = __half22float2(b0), f2hi = __half22float2(b1);

        float4 r;
        r.x = (v0.x + f1lo.x + f2lo.x + acc.x) * 0.25f;
        r.y = (v0.y + f1lo.y + f2lo.y + acc.y) * 0.25f;
        r.z = (v0.z + f1hi.x + f2hi.x + acc.z) * 0.25f;
        r.w = (v0.w + f1hi.y + f2hi.y + acc.w) * 0.25f;
        *(float4*)(out + (size_t)gw * D + subl * 4) = r;
    }
}

extern "C" void kernel_launch(void* const* d_in, const int* in_sizes, int n_in,
                              void* d_out, int out_size) {
    const int*   rows1 = (const int*)  d_in[0];
    const int*   cols1 = (const int*)  d_in[1];
    const float* vals1 = (const float*)d_in[2];
    const int*   rows2 = (const int*)  d_in[3];
    const int*   cols2 = (const int*)  d_in[4];
    const float* vals2 = (const float*)d_in[5];
    const float* ue1   = (const float*)d_in[6];
    const float* ie1   = (const float*)d_in[7];
    const float* ue2   = (const float*)d_in[8];
    const float* ie2   = (const float*)d_in[9];
    const int*   u1    = (const int*)  d_in[10];
    const int*   p1    = (const int*)  d_in[11];
    const int*   n1    = (const int*)  d_in[12];
    const int*   u2    = (const int*)  d_in[13];
    const int*   p2    = (const int*)  d_in[14];
    const int*   n2    = (const int*)  d_in[15];
    float* out = (float*)d_out;

    const int nnz1 = in_sizes[0];
    const int nnz2 = in_sizes[3];
    const int TPB = 256;
    const int scan_blocks1 = (nnz1 + TPB - 1) / TPB;
    const int scan_blocks2 = (nnz2 + TPB - 1) / TPB;
    const int spmm_blocks  = (int)(((size_t)NTOT * 32 + TPB - 1) / TPB);

    // ---- graph 1: (ue1|ie1) -> h1a -> h2a ----
    rowptr_scan_kernel<0><<<scan_blocks1, TPB>>>(rows1, nnz1);
    spmm_first_kernel<0, 0><<<spmm_blocks, TPB>>>(cols1, vals1, ue1, ie1);
    spmm_mid_kernel<0, 1, 0><<<spmm_blocks, TPB>>>(cols1, vals1);

    // ---- graph 2: (ue2|ie2) -> h1b -> h2b ----
    rowptr_scan_kernel<1><<<scan_blocks2, TPB>>>(rows2, nnz2);
    spmm_first_kernel<2, 1><<<spmm_blocks, TPB>>>(cols2, vals2, ue2, ie2);
    spmm_mid_kernel<2, 3, 1><<<spmm_blocks, TPB>>>(cols2, vals2);

    // ---- fused layer-3 + mean + gather ----
    const int gather_blocks = (6 * BATCH * 32 + TPB - 1) / TPB;
    gather3_kernel<<<gather_blocks, TPB>>>(u1, p1, n1, u2, p2, n2,
                                           cols1, vals1, cols2, vals2,
                                           ue1, ie1, ue2, ie2, out);
}

// round 16
// speedup vs baseline: 1.8490x; 1.0183x over previous
#include <cuda_runtime.h>
#include <cuda_fp16.h>
#include <cstdint>
#include <cstring>

#define N_USERS 100000
#define N_ITEMS 50000
#define NTOT    150000
#define D       64
#define BATCH   4096

// -------- static scratch: fp16 e0,e1,e2 per graph --------
__device__ __half g_h0a[(size_t)NTOT * D];
__device__ __half g_h1a[(size_t)NTOT * D];
__device__ __half g_h2a[(size_t)NTOT * D];
__device__ __half g_h0b[(size_t)NTOT * D];
__device__ __half g_h1b[(size_t)NTOT * D];
__device__ __half g_h2b[(size_t)NTOT * D];
__device__ int    g_rowptr1[NTOT + 1];
__device__ int    g_rowptr2[NTOT + 1];

template <int W> __device__ __forceinline__ __half* hbuf();
template <> __device__ __forceinline__ __half* hbuf<0>() { return g_h0a; }
template <> __device__ __forceinline__ __half* hbuf<1>() { return g_h1a; }
template <> __device__ __forceinline__ __half* hbuf<2>() { return g_h2a; }
template <> __device__ __forceinline__ __half* hbuf<3>() { return g_h0b; }
template <> __device__ __forceinline__ __half* hbuf<4>() { return g_h1b; }
template <> __device__ __forceinline__ __half* hbuf<5>() { return g_h2b; }
template <int W> __device__ __forceinline__ int* rptr() {
    return W == 0 ? g_rowptr1 : g_rowptr2;
}

// 4-wide scan-based rowptr: rp[r] = lower_bound(rows, r).
template <int WHICH>
__global__ void rowptr_scan_kernel(const int* __restrict__ rows, int nnz) {
    int t    = blockIdx.x * blockDim.x + threadIdx.x;
    int base = t * 4;
    if (base >= nnz) return;
    int* rp = rptr<WHICH>();

    int prev = (base == 0) ? -1 : __ldg(rows + base - 1);
    int4 cur4 = *(const int4*)(rows + base);           // nnz assumed %4; guarded below
    int c[4] = {cur4.x, cur4.y, cur4.z, cur4.w};
    #pragma unroll
    for (int k = 0; k < 4; ++k) {
        int i = base + k;
        if (i >= nnz) break;
        int cur = c[k];
        for (int r = prev + 1; r <= cur; ++r) rp[r] = i;   // (prev, cur] -> i
        prev = cur;
        if (i == nnz - 1)
            for (int r = cur + 1; r <= NTOT; ++r) rp[r] = nnz;
    }
}

// concat(ue, ie) -> fp16 table
template <int OUT>
__global__ void pack_h_kernel(const float* __restrict__ ue, const float* __restrict__ ie) {
    size_t i = (size_t)blockIdx.x * blockDim.x + threadIdx.x;  // float4 index
    const size_t total = (size_t)NTOT * D / 4;
    if (i >= total) return;
    const size_t nu = (size_t)N_USERS * D / 4;
    float4 v = (i < nu) ? __ldg((const float4*)ue + i)
                        : __ldg((const float4*)ie + (i - nu));
    __half2 h0 = __floats2half2_rn(v.x, v.y);
    __half2 h1 = __floats2half2_rn(v.z, v.w);
    uint2 u;
    memcpy(&u.x, &h0, 4);
    memcpy(&u.y, &h1, 4);
    *((uint2*)hbuf<OUT>() + i) = u;
}

__device__ __forceinline__ void store_half4(__half* out, size_t off, float4 a) {
    __half2 h0 = __floats2half2_rn(a.x, a.y);
    __half2 h1 = __floats2half2_rn(a.z, a.w);
    uint2 u;
    memcpy(&u.x, &h0, 4);
    memcpy(&u.y, &h1, 4);
    *(uint2*)(out + off) = u;
}

// fp16-gather row reduction: half-warp per edge, LDG.64 rows (128B/row), fp32 acc.
__device__ __forceinline__ float4 row_reduce_f16(
    const int* __restrict__ cols, const float* __restrict__ vals,
    const __half* __restrict__ tab, int s, int e, int half, int subl)
{
    float4 acc = make_float4(0.f, 0.f, 0.f, 0.f);
    int nfull = (e - s) & ~7;
    int j = s;
    for (; j < s + nfull; j += 8) {
        #pragma unroll
        for (int k = 0; k < 4; ++k) {
            int je = j + 2 * k + half;
            int   c = __ldg(cols + je);
            float v = __ldg(vals + je);
            uint2 u = __ldcg((const uint2*)(tab + (size_t)c * D + subl * 4));
            __half2 h0, h1;
            memcpy(&h0, &u.x, 4);
            memcpy(&h1, &u.y, 4);
            float2 f0 = __half22float2(h0);
            float2 f1 = __half22float2(h1);
            acc.x = fmaf(v, f0.x, acc.x);
            acc.y = fmaf(v, f0.y, acc.y);
            acc.z = fmaf(v, f1.x, acc.z);
            acc.w = fmaf(v, f1.y, acc.w);
        }
    }
    if (j < e) {
        #pragma unroll
        for (int k = 0; k < 4; ++k) {
            int je = j + 2 * k + half;
            int jc = je < e ? je : e - 1;
            int   c = __ldg(cols + jc);
            float v = (je < e) ? __ldg(vals + jc) : 0.f;
            uint2 u = __ldcg((const uint2*)(tab + (size_t)c * D + subl * 4));
            __half2 h0, h1;
            memcpy(&h0, &u.x, 4);
            memcpy(&h1, &u.y, 4);
            float2 f0 = __half22float2(h0);
            float2 f1 = __half22float2(h1);
            acc.x = fmaf(v, f0.x, acc.x);
            acc.y = fmaf(v, f0.y, acc.y);
            acc.z = fmaf(v, f1.x, acc.z);
            acc.w = fmaf(v, f1.y, acc.w);
        }
    }
    acc.x += __shfl_xor_sync(0xFFFFFFFFu, acc.x, 16);
    acc.y += __shfl_xor_sync(0xFFFFFFFFu, acc.y, 16);
    acc.z += __shfl_xor_sync(0xFFFFFFFFu, acc.z, 16);
    acc.w += __shfl_xor_sync(0xFFFFFFFFu, acc.w, 16);
    return acc;
}

// SpMM layer: fp16 gather -> fp16 store
template <int IN, int OUT, int WHICH>
__global__ void __launch_bounds__(256, 8)
spmm_kernel(const int* __restrict__ cols, const float* __restrict__ vals) {
    int gw   = (int)((blockIdx.x * blockDim.x + threadIdx.x) >> 5);
    int lane = threadIdx.x & 31;
    if (gw >= NTOT) return;
    const int* rp = rptr<WHICH>();
    int s = __ldg(rp + gw);
    int e = __ldg(rp + gw + 1);
    int half = lane >> 4, subl = lane & 15;
    float4 acc = row_reduce_f16(cols, vals, hbuf<IN>(), s, e, half, subl);
    if (half == 0)
        store_half4(hbuf<OUT>(), (size_t)gw * D + subl * 4, acc);
}

// Fused layer-3 + mean + gather (fp32 output, e0 from raw fp32 inputs):
//   out[seg,b,:] = (e0[idx] + e1h[idx] + e2h[idx] + (A·e2h)[idx]) / 4
__global__ void __launch_bounds__(256, 8)
gather3_kernel(const int* __restrict__ u1, const int* __restrict__ p1,
               const int* __restrict__ n1, const int* __restrict__ u2,
               const int* __restrict__ p2, const int* __restrict__ n2,
               const int* __restrict__ cols1, const float* __restrict__ vals1,
               const int* __restrict__ cols2, const float* __restrict__ vals2,
               const float* __restrict__ ue1, const float* __restrict__ ie1,
               const float* __restrict__ ue2, const float* __restrict__ ie2,
               float* __restrict__ out) {
    int gw   = (int)((blockIdx.x * blockDim.x + threadIdx.x) >> 5);
    int lane = threadIdx.x & 31;
    if (gw >= 6 * BATCH) return;
    int seg = gw / BATCH;
    int b   = gw - seg * BATCH;

    int idx; int g2;
    switch (seg) {
        case 0:  idx = __ldg(u1 + b);           g2 = 0; break;
        case 1:  idx = N_USERS + __ldg(p1 + b); g2 = 0; break;
        case 2:  idx = N_USERS + __ldg(n1 + b); g2 = 0; break;
        case 3:  idx = __ldg(u2 + b);           g2 = 1; break;
        case 4:  idx = N_USERS + __ldg(p2 + b); g2 = 1; break;
        default: idx = N_USERS + __ldg(n2 + b); g2 = 1; break;
    }

    const int*    rp   = g2 ? g_rowptr2 : g_rowptr1;
    const int*    cols = g2 ? cols2 : cols1;
    const float*  vals = g2 ? vals2 : vals1;
    const __half* e1t  = g2 ? g_h1b : g_h1a;
    const __half* e2t  = g2 ? g_h2b : g_h2a;

    int s = __ldg(rp + idx);
    int e = __ldg(rp + idx + 1);
    int half = lane >> 4, subl = lane & 15;

    // e3[idx] on the fly from fp16 e2
    float4 acc = row_reduce_f16(cols, vals, e2t, s, e, half, subl);

    if (half == 0) {
        const float* e0base;
        if (idx < N_USERS) e0base = (g2 ? ue2 : ue1) + (size_t)idx * D;
        else               e0base = (g2 ? ie2 : ie1) + (size_t)(idx - N_USERS) * D;
        size_t o = (size_t)idx * D + subl * 4;
        float4 v0 = *(const float4*)(e0base + subl * 4);

        uint2 ua = *(const uint2*)(e1t + o);
        uint2 ub = *(const uint2*)(e2t + o);
        __half2 a0, a1, b0, b1;
        memcpy(&a0, &ua.x, 4); memcpy(&a1, &ua.y, 4);
        memcpy(&b0, &ub.x, 4); memcpy(&b1, &ub.y, 4);
        float2 f1lo = __half22float2(a0), f1hi = __half22float2(a1);
        float2 f2lo = __half22float2(b0), f2hi = __half22float2(b1);

        float4 r;
        r.x = (v0.x + f1lo.x + f2lo.x + acc.x) * 0.25f;
        r.y = (v0.y + f1lo.y + f2lo.y + acc.y) * 0.25f;
        r.z = (v0.z + f1hi.x + f2hi.x + acc.z) * 0.25f;
        r.w = (v0.w + f1hi.y + f2hi.y + acc.w) * 0.25f;
        *(float4*)(out + (size_t)gw * D + subl * 4) = r;
    }
}

extern "C" void kernel_launch(void* const* d_in, const int* in_sizes, int n_in,
                              void* d_out, int out_size) {
    const int*   rows1 = (const int*)  d_in[0];
    const int*   cols1 = (const int*)  d_in[1];
    const float* vals1 = (const float*)d_in[2];
    const int*   rows2 = (const int*)  d_in[3];
    const int*   cols2 = (const int*)  d_in[4];
    const float* vals2 = (const float*)d_in[5];
    const float* ue1   = (const float*)d_in[6];
    const float* ie1   = (const float*)d_in[7];
    const float* ue2   = (const float*)d_in[8];
    const float* ie2   = (const float*)d_in[9];
    const int*   u1    = (const int*)  d_in[10];
    const int*   p1    = (const int*)  d_in[11];
    const int*   n1    = (const int*)  d_in[12];
    const int*   u2    = (const int*)  d_in[13];
    const int*   p2    = (const int*)  d_in[14];
    const int*   n2    = (const int*)  d_in[15];
    float* out = (float*)d_out;

    const int nnz1 = in_sizes[0];
    const int nnz2 = in_sizes[3];
    const int TPB = 256;
    const int scan_blocks1 = ((nnz1 + 3) / 4 + TPB - 1) / TPB;
    const int scan_blocks2 = ((nnz2 + 3) / 4 + TPB - 1) / TPB;
    const int pack_blocks  = (int)(((size_t)NTOT * D / 4 + TPB - 1) / TPB);
    const int spmm_blocks  = (int)(((size_t)NTOT * 32 + TPB - 1) / TPB);

    // ---- graph 1: pack -> h0a -> h1a -> h2a ----
    rowptr_scan_kernel<0><<<scan_blocks1, TPB>>>(rows1, nnz1);
    pack_h_kernel<0><<<pack_blocks, TPB>>>(ue1, ie1);
    spmm_kernel<0, 1, 0><<<spmm_blocks, TPB>>>(cols1, vals1);
    spmm_kernel<1, 2, 0><<<spmm_blocks, TPB>>>(cols1, vals1);

    // ---- graph 2: pack -> h0b -> h1b -> h2b ----
    rowptr_scan_kernel<1><<<scan_blocks2, TPB>>>(rows2, nnz2);
    pack_h_kernel<3><<<pack_blocks, TPB>>>(ue2, ie2);
    spmm_kernel<3, 4, 1><<<spmm_blocks, TPB>>>(cols2, vals2);
    spmm_kernel<4, 5, 1><<<spmm_blocks, TPB>>>(cols2, vals2);

    // ---- fused layer-3 + mean + gather ----
    const int gather_blocks = (6 * BATCH * 32 + TPB - 1) / TPB;
    gather3_kernel<<<gather_blocks, TPB>>>(u1, p1, n1, u2, p2, n2,
                                           cols1, vals1, cols2, vals2,
                                           ue1, ie1, ue2, ie2, out);
}

// round 17
// speedup vs baseline: 1.9335x; 1.0457x over previous
#include <cuda_runtime.h>
#include <cuda_fp16.h>
#include <cstdint>
#include <cstring>

#define N_USERS 100000
#define N_ITEMS 50000
#define NTOT    150000
#define D       64
#define BATCH   4096

// -------- static scratch: fp16 e0,e1,e2 per graph --------
__device__ __half g_h0a[(size_t)NTOT * D];
__device__ __half g_h1a[(size_t)NTOT * D];
__device__ __half g_h2a[(size_t)NTOT * D];
__device__ __half g_h0b[(size_t)NTOT * D];
__device__ __half g_h1b[(size_t)NTOT * D];
__device__ __half g_h2b[(size_t)NTOT * D];
__device__ int    g_rowptr1[NTOT + 1];
__device__ int    g_rowptr2[NTOT + 1];

template <int W> __device__ __forceinline__ __half* hbuf();
template <> __device__ __forceinline__ __half* hbuf<0>() { return g_h0a; }
template <> __device__ __forceinline__ __half* hbuf<1>() { return g_h1a; }
template <> __device__ __forceinline__ __half* hbuf<2>() { return g_h2a; }
template <> __device__ __forceinline__ __half* hbuf<3>() { return g_h0b; }
template <> __device__ __forceinline__ __half* hbuf<4>() { return g_h1b; }
template <> __device__ __forceinline__ __half* hbuf<5>() { return g_h2b; }
template <int W> __device__ __forceinline__ int* rptr() {
    return W == 0 ? g_rowptr1 : g_rowptr2;
}

// 4-wide scan-based rowptr: rp[r] = lower_bound(rows, r).
template <int WHICH>
__global__ void rowptr_scan_kernel(const int* __restrict__ rows, int nnz) {
    int t    = blockIdx.x * blockDim.x + threadIdx.x;
    int base = t * 4;
    if (base >= nnz) return;
    int* rp = rptr<WHICH>();

    int prev = (base == 0) ? -1 : __ldg(rows + base - 1);
    #pragma unroll
    for (int k = 0; k < 4; ++k) {
        int i = base + k;
        if (i >= nnz) break;
        int cur = __ldg(rows + i);
        for (int r = prev + 1; r <= cur; ++r) rp[r] = i;   // (prev, cur] -> i
        prev = cur;
        if (i == nnz - 1)
            for (int r = cur + 1; r <= NTOT; ++r) rp[r] = nnz;
    }
}

// concat(ue, ie) -> fp16 table
template <int OUT>
__global__ void pack_h_kernel(const float* __restrict__ ue, const float* __restrict__ ie) {
    size_t i = (size_t)blockIdx.x * blockDim.x + threadIdx.x;  // float4 index
    const size_t total = (size_t)NTOT * D / 4;
    if (i >= total) return;
    const size_t nu = (size_t)N_USERS * D / 4;
    float4 v = (i < nu) ? __ldg((const float4*)ue + i)
                        : __ldg((const float4*)ie + (i - nu));
    __half2 h0 = __floats2half2_rn(v.x, v.y);
    __half2 h1 = __floats2half2_rn(v.z, v.w);
    uint2 u;
    memcpy(&u.x, &h0, 4);
    memcpy(&u.y, &h1, 4);
    *((uint2*)hbuf<OUT>() + i) = u;
}

// Quarter-warp fp16 row reduction:
//   q = lane>>3 (one edge per 8-lane quarter), sub = lane&7 (16B slot in 128B row).
//   One LDG.128 gathers 4 edges' rows; col/val: one LDG each per 4 edges.
//   fp32 accumulate; cross-quarter combine via shfl_xor(8) + shfl_xor(16).
__device__ __forceinline__ void row_reduce_f16_q(
    const int* __restrict__ cols, const float* __restrict__ vals,
    const __half* __restrict__ tab, int s, int e, int q, int sub,
    float acc[8])
{
    #pragma unroll
    for (int i = 0; i < 8; ++i) acc[i] = 0.f;

    int nfull = (e - s) & ~7;
    int j = s;
    for (; j < s + nfull; j += 8) {            // 8 edges per iter (2 per quarter)
        #pragma unroll
        for (int k = 0; k < 2; ++k) {
            int je = j + 4 * k + q;
            int   c = __ldg(cols + je);
            float v = __ldg(vals + je);
            uint4 u = __ldcg((const uint4*)(tab + (size_t)c * D + sub * 8));
            __half2 h0, h1, h2, h3;
            memcpy(&h0, &u.x, 4); memcpy(&h1, &u.y, 4);
            memcpy(&h2, &u.z, 4); memcpy(&h3, &u.w, 4);
            float2 f0 = __half22float2(h0), f1 = __half22float2(h1);
            float2 f2 = __half22float2(h2), f3 = __half22float2(h3);
            acc[0] = fmaf(v, f0.x, acc[0]); acc[1] = fmaf(v, f0.y, acc[1]);
            acc[2] = fmaf(v, f1.x, acc[2]); acc[3] = fmaf(v, f1.y, acc[3]);
            acc[4] = fmaf(v, f2.x, acc[4]); acc[5] = fmaf(v, f2.y, acc[5]);
            acc[6] = fmaf(v, f3.x, acc[6]); acc[7] = fmaf(v, f3.y, acc[7]);
        }
    }
    if (j < e) {                                // one clamped 8-edge tail
        #pragma unroll
        for (int k = 0; k < 2; ++k) {
            int je = j + 4 * k + q;
            int jc = je < e ? je : e - 1;
            int   c = __ldg(cols + jc);
            float v = (je < e) ? __ldg(vals + jc) : 0.f;
            uint4 u = __ldcg((const uint4*)(tab + (size_t)c * D + sub * 8));
            __half2 h0, h1, h2, h3;
            memcpy(&h0, &u.x, 4); memcpy(&h1, &u.y, 4);
            memcpy(&h2, &u.z, 4); memcpy(&h3, &u.w, 4);
            float2 f0 = __half22float2(h0), f1 = __half22float2(h1);
            float2 f2 = __half22float2(h2), f3 = __half22float2(h3);
            acc[0] = fmaf(v, f0.x, acc[0]); acc[1] = fmaf(v, f0.y, acc[1]);
            acc[2] = fmaf(v, f1.x, acc[2]); acc[3] = fmaf(v, f1.y, acc[3]);
            acc[4] = fmaf(v, f2.x, acc[4]); acc[5] = fmaf(v, f2.y, acc[5]);
            acc[6] = fmaf(v, f3.x, acc[6]); acc[7] = fmaf(v, f3.y, acc[7]);
        }
    }

    #pragma unroll
    for (int i = 0; i < 8; ++i) {
        acc[i] += __shfl_xor_sync(0xFFFFFFFFu, acc[i], 8);
        acc[i] += __shfl_xor_sync(0xFFFFFFFFu, acc[i], 16);
    }
}

__device__ __forceinline__ void store_half8(__half* out, size_t off, const float acc[8]) {
    __half2 h0 = __floats2half2_rn(acc[0], acc[1]);
    __half2 h1 = __floats2half2_rn(acc[2], acc[3]);
    __half2 h2 = __floats2half2_rn(acc[4], acc[5]);
    __half2 h3 = __floats2half2_rn(acc[6], acc[7]);
    uint4 u;
    memcpy(&u.x, &h0, 4); memcpy(&u.y, &h1, 4);
    memcpy(&u.z, &h2, 4); memcpy(&u.w, &h3, 4);
    *(uint4*)(out + off) = u;
}

// SpMM layer: fp16 gather -> fp16 store (warp per row, quarter-warp per edge)
template <int IN, int OUT, int WHICH>
__global__ void __launch_bounds__(256, 8)
spmm_kernel(const int* __restrict__ cols, const float* __restrict__ vals) {
    int gw   = (int)((blockIdx.x * blockDim.x + threadIdx.x) >> 5);
    int lane = threadIdx.x & 31;
    if (gw >= NTOT) return;
    const int* rp = rptr<WHICH>();
    int s = __ldg(rp + gw);
    int e = __ldg(rp + gw + 1);
    int q = lane >> 3, sub = lane & 7;
    float acc[8];
    row_reduce_f16_q(cols, vals, hbuf<IN>(), s, e, q, sub, acc);
    if (q == 0)
        store_half8(hbuf<OUT>(), (size_t)gw * D + sub * 8, acc);
}

// Fused layer-3 + mean + gather (fp32 output, e0 from raw fp32 inputs):
//   out[seg,b,:] = (e0[idx] + e1h[idx] + e2h[idx] + (A·e2h)[idx]) / 4
__global__ void __launch_bounds__(256, 8)
gather3_kernel(const int* __restrict__ u1, const int* __restrict__ p1,
               const int* __restrict__ n1, const int* __restrict__ u2,
               const int* __restrict__ p2, const int* __restrict__ n2,
               const int* __restrict__ cols1, const float* __restrict__ vals1,
               const int* __restrict__ cols2, const float* __restrict__ vals2,
               const float* __restrict__ ue1, const float* __restrict__ ie1,
               const float* __restrict__ ue2, const float* __restrict__ ie2,
               float* __restrict__ out) {
    int gw   = (int)((blockIdx.x * blockDim.x + threadIdx.x) >> 5);
    int lane = threadIdx.x & 31;
    if (gw >= 6 * BATCH) return;
    int seg = gw / BATCH;
    int b   = gw - seg * BATCH;

    int idx; int g2;
    switch (seg) {
        case 0:  idx = __ldg(u1 + b);           g2 = 0; break;
        case 1:  idx = N_USERS + __ldg(p1 + b); g2 = 0; break;
        case 2:  idx = N_USERS + __ldg(n1 + b); g2 = 0; break;
        case 3:  idx = __ldg(u2 + b);           g2 = 1; break;
        case 4:  idx = N_USERS + __ldg(p2 + b); g2 = 1; break;
        default: idx = N_USERS + __ldg(n2 + b); g2 = 1; break;
    }

    const int*    rp   = g2 ? g_rowptr2 : g_rowptr1;
    const int*    cols = g2 ? cols2 : cols1;
    const float*  vals = g2 ? vals2 : vals1;
    const __half* e1t  = g2 ? g_h1b : g_h1a;
    const __half* e2t  = g2 ? g_h2b : g_h2a;

    int s = __ldg(rp + idx);
    int e = __ldg(rp + idx + 1);
    int q = lane >> 3, sub = lane & 7;

    // e3[idx] on the fly from fp16 e2
    float acc[8];
    row_reduce_f16_q(cols, vals, e2t, s, e, q, sub, acc);

    if (q == 0) {
        const float* e0base;
        if (idx < N_USERS) e0base = (g2 ? ue2 : ue1) + (size_t)idx * D;
        else               e0base = (g2 ? ie2 : ie1) + (size_t)(idx - N_USERS) * D;
        float4 a0 = __ldg((const float4*)(e0base + sub * 8));
        float4 a1 = __ldg((const float4*)(e0base + sub * 8 + 4));

        size_t o = (size_t)idx * D + sub * 8;
        uint4 ua = *(const uint4*)(e1t + o);
        uint4 ub = *(const uint4*)(e2t + o);
        __half2 x0, x1, x2, x3, y0, y1, y2, y3;
        memcpy(&x0, &ua.x, 4); memcpy(&x1, &ua.y, 4);
        memcpy(&x2, &ua.z, 4); memcpy(&x3, &ua.w, 4);
        memcpy(&y0, &ub.x, 4); memcpy(&y1, &ub.y, 4);
        memcpy(&y2, &ub.z, 4); memcpy(&y3, &ub.w, 4);
        float2 e1f[4] = {__half22float2(x0), __half22float2(x1),
                         __half22float2(x2), __half22float2(x3)};
        float2 e2f[4] = {__half22float2(y0), __half22float2(y1),
                         __half22float2(y2), __half22float2(y3)};

        float4 r0, r1;
        r0.x = (a0.x + e1f[0].x + e2f[0].x + acc[0]) * 0.25f;
        r0.y = (a0.y + e1f[0].y + e2f[0].y + acc[1]) * 0.25f;
        r0.z = (a0.z + e1f[1].x + e2f[1].x + acc[2]) * 0.25f;
        r0.w = (a0.w + e1f[1].y + e2f[1].y + acc[3]) * 0.25f;
        r1.x = (a1.x + e1f[2].x + e2f[2].x + acc[4]) * 0.25f;
        r1.y = (a1.y + e1f[2].y + e2f[2].y + acc[5]) * 0.25f;
        r1.z = (a1.z + e1f[3].x + e2f[3].x + acc[6]) * 0.25f;
        r1.w = (a1.w + e1f[3].y + e2f[3].y + acc[7]) * 0.25f;
        *(float4*)(out + (size_t)gw * D + sub * 8)     = r0;
        *(float4*)(out + (size_t)gw * D + sub * 8 + 4) = r1;
    }
}

extern "C" void kernel_launch(void* const* d_in, const int* in_sizes, int n_in,
                              void* d_out, int out_size) {
    const int*   rows1 = (const int*)  d_in[0];
    const int*   cols1 = (const int*)  d_in[1];
    const float* vals1 = (const float*)d_in[2];
    const int*   rows2 = (const int*)  d_in[3];
    const int*   cols2 = (const int*)  d_in[4];
    const float* vals2 = (const float*)d_in[5];
    const float* ue1   = (const float*)d_in[6];
    const float* ie1   = (const float*)d_in[7];
    const float* ue2   = (const float*)d_in[8];
    const float* ie2   = (const float*)d_in[9];
    const int*   u1    = (const int*)  d_in[10];
    const int*   p1    = (const int*)  d_in[11];
    const int*   n1    = (const int*)  d_in[12];
    const int*   u2    = (const int*)  d_in[13];
    const int*   p2    = (const int*)  d_in[14];
    const int*   n2    = (const int*)  d_in[15];
    float* out = (float*)d_out;

    const int nnz1 = in_sizes[0];
    const int nnz2 = in_sizes[3];
    const int TPB = 256;
    const int scan_blocks1 = ((nnz1 + 3) / 4 + TPB - 1) / TPB;
    const int scan_blocks2 = ((nnz2 + 3) / 4 + TPB - 1) / TPB;
    const int pack_blocks  = (int)(((size_t)NTOT * D / 4 + TPB - 1) / TPB);
    const int spmm_blocks  = (int)(((size_t)NTOT * 32 + TPB - 1) / TPB);

    // ---- graph 1: pack -> h0a -> h1a -> h2a ----
    rowptr_scan_kernel<0><<<scan_blocks1, TPB>>>(rows1, nnz1);
    pack_h_kernel<0><<<pack_blocks, TPB>>>(ue1, ie1);
    spmm_kernel<0, 1, 0><<<spmm_blocks, TPB>>>(cols1, vals1);
    spmm_kernel<1, 2, 0><<<spmm_blocks, TPB>>>(cols1, vals1);

    // ---- graph 2: pack -> h0b -> h1b -> h2b ----
    rowptr_scan_kernel<1><<<scan_blocks2, TPB>>>(rows2, nnz2);
    pack_h_kernel<3><<<pack_blocks, TPB>>>(ue2, ie2);
    spmm_kernel<3, 4, 1><<<spmm_blocks, TPB>>>(cols2, vals2);
    spmm_kernel<4, 5, 1><<<spmm_blocks, TPB>>>(cols2, vals2);

    // ---- fused layer-3 + mean + gather ----
    const int gather_blocks = (6 * BATCH * 32 + TPB - 1) / TPB;
    gather3_kernel<<<gather_blocks, TPB>>>(u1, p1, n1, u2, p2, n2,
                                           cols1, vals1, cols2, vals2,
                                           ue1, ie1, ue2, ie2, out);
}